// round 8
// baseline (speedup 1.0000x reference)
#include <cuda_runtime.h>
#include <math.h>

// Problem constants
#define BT     8192      // B*T tokens
#define KDIM   4096      // N*C flattened
#define CDIM   1024      // embed
#define NOUT   24        // 4 pre + 4 post + 16 res
#define EPSV   1e-6f

// Fused kernel tiling
#define TMF    8                 // tokens per block
#define NTF    256               // threads (8 warps)
#define KCF    512               // k-chunk
#define NCHF   (KDIM / KCF)      // 8 chunks
#define SP     4100              // stream tile pitch (floats); 4100%32=4 -> conflict-free frags
#define WPc    516               // weight tile pitch (floats); 516%32=4

#define SMEM_BYTES ((TMF * SP + NOUT * WPc) * 4)   // 180736

__device__ __forceinline__ unsigned f2tf32(float x) {
    unsigned u;
    asm("cvt.rna.tf32.f32 %0, %1;" : "=r"(u) : "f"(x));
    return u;
}

__device__ __forceinline__ void mma_tf32(float c[4], const unsigned a[4],
                                         const unsigned b[2]) {
    asm volatile(
        "mma.sync.aligned.m16n8k8.row.col.f32.tf32.tf32.f32 "
        "{%0,%1,%2,%3}, {%4,%5,%6,%7}, {%8,%9}, {%0,%1,%2,%3};"
        : "+f"(c[0]), "+f"(c[1]), "+f"(c[2]), "+f"(c[3])
        : "r"(a[0]), "r"(a[1]), "r"(a[2]), "r"(a[3]), "r"(b[0]), "r"(b[1]));
}

// ---------------------------------------------------------------------------
// Fused: gate GEMM (tf32 mma) + sumsq + gate math + combine, ONE stream read.
// Block = 8 tokens. Stream tile (8 x 4096 fp32, 128KB) is smem-resident for
// the whole block lifetime: phase 1 computes gates from it, phase 2 combines
// from it. Weights staged per 512-chunk as tf32 (k split across 8 warps).
// ---------------------------------------------------------------------------
__global__ void __launch_bounds__(NTF, 1)
fused_mhc(const float* __restrict__ stream,
          const float* __restrict__ outv,
          const float* __restrict__ w_pre,
          const float* __restrict__ w_post,
          const float* __restrict__ w_res,
          const float* __restrict__ b_pre,
          const float* __restrict__ b_post,
          const float* __restrict__ b_res,
          const float* __restrict__ a_pre,
          const float* __restrict__ a_post,
          const float* __restrict__ a_res,
          float* __restrict__ xin,
          float* __restrict__ upd)
{
    extern __shared__ float sm[];
    float*    Sf  = sm;                       // [8][SP] fp32 stream tile (persistent)
    float*    Wtf = sm + TMF * SP;            // [24][WPc] weight chunk (tf32 bits)
    unsigned* Wt  = (unsigned*)Wtf;

    __shared__ float ssb[4][256];             // per-thread sumsq partials
    __shared__ float gsm[TMF][26];            // final gates per token

    const int tid  = threadIdx.x;
    const int lane = tid & 31;
    const int w    = tid >> 5;                // warp id
    const int gid  = lane >> 2;               // mma group (0..7) == token row
    const int tig  = lane & 3;
    const int tok0 = blockIdx.x * TMF;

    float c[3][4];                            // [n-tile][frag]; rows gid (c0,c1) used
#pragma unroll
    for (int nt = 0; nt < 3; ++nt)
#pragma unroll
        for (int q = 0; q < 4; ++q) c[nt][q] = 0.f;
    float ss[4] = {0.f, 0.f, 0.f, 0.f};

    // ===================== Phase 1: gate GEMM ============================
    for (int ch = 0; ch < NCHF; ++ch) {
        if (ch) __syncthreads();              // Wt consumed by prior mma
        // ---- stage stream chunk: 8 x 512 fp32 (1024 float4, 4/thread) ----
#pragma unroll
        for (int i = 0; i < 4; ++i) {
            int f   = tid + NTF * i;          // 0..1023
            int row = f >> 7;                 // 0..7 (const per warp)
            int c4  = f & 127;
            float4 v = *(const float4*)(stream + (size_t)(tok0 + row) * KDIM
                                        + ch * KCF + c4 * 4);
            ss[i] += v.x * v.x + v.y * v.y + v.z * v.z + v.w * v.w;
            *(float4*)(Sf + row * SP + ch * KCF + c4 * 4) = v;
        }
        // ---- stage weight chunk: 24 x 512 -> tf32 (3072 float4, 12/thread) ----
#pragma unroll
        for (int j = 0; j < 12; ++j) {
            int f   = tid + NTF * j;          // 0..3071
            int row = f >> 7;                 // 0..23 (const per warp)
            int c4  = f & 127;
            const float* src = (row < 4)  ? (w_pre  + (size_t)row * KDIM)
                             : (row < 8)  ? (w_post + (size_t)(row - 4) * KDIM)
                                          : (w_res  + (size_t)(row - 8) * KDIM);
            float4 v = *(const float4*)(src + ch * KCF + c4 * 4);
            unsigned* d = Wt + row * WPc + c4 * 4;
            d[0] = f2tf32(v.x); d[1] = f2tf32(v.y);
            d[2] = f2tf32(v.z); d[3] = f2tf32(v.w);
        }
        __syncthreads();
        // ---- mma: warp w covers cols [w*64, w*64+64) = 8 k-steps ----
#pragma unroll
        for (int s = 0; s < 8; ++s) {
            const int kk = w * 64 + 8 * s;
            unsigned a[4];
            a[0] = f2tf32(Sf[gid * SP + ch * KCF + kk + tig]);
            a[2] = f2tf32(Sf[gid * SP + ch * KCF + kk + tig + 4]);
            a[1] = a[0]; a[3] = a[2];         // M-rows 8..15 unused
#pragma unroll
            for (int nt = 0; nt < 3; ++nt) {
                unsigned b[2];
                b[0] = Wt[(nt * 8 + gid) * WPc + kk + tig];
                b[1] = Wt[(nt * 8 + gid) * WPc + kk + tig + 4];
                mma_tf32(c[nt], a, b);
            }
        }
    }
    __syncthreads();                          // Wt region now dead -> reuse

    // ===================== Reduction + gate math =========================
    float* red = Wtf;                         // [8 warps][8 tok][26]
    float* Gp  = Wtf + 8 * TMF * 26;          // [8 tok][26]

#pragma unroll
    for (int nt = 0; nt < 3; ++nt) {
        int o = nt * 8 + 2 * tig;
        red[(w * TMF + gid) * 26 + o]     = c[nt][0];
        red[(w * TMF + gid) * 26 + o + 1] = c[nt][1];
    }
#pragma unroll
    for (int i = 0; i < 4; ++i) ssb[i][tid] = ss[i];
    __syncthreads();

    if (tid < TMF * NOUT) {                   // 192 sums
        int t = tid / NOUT, o = tid - t * NOUT;
        float s = 0.f;
#pragma unroll
        for (int ww = 0; ww < 8; ++ww)
            s += red[(ww * TMF + t) * 26 + o];
        Gp[t * 26 + o] = s;
    }
    {   // sumsq: warp w reduces token row w
        int i = w >> 1, b = w & 1;
        float s = 0.f;
#pragma unroll
        for (int j = 0; j < 4; ++j) s += ssb[i][b * 128 + lane + 32 * j];
        s += __shfl_xor_sync(0xffffffffu, s, 16);
        s += __shfl_xor_sync(0xffffffffu, s, 8);
        s += __shfl_xor_sync(0xffffffffu, s, 4);
        s += __shfl_xor_sync(0xffffffffu, s, 2);
        s += __shfl_xor_sync(0xffffffffu, s, 1);
        if (lane == 0) Gp[w * 26 + 24] = s;
    }
    __syncthreads();

    if (tid < TMF) {                          // one thread per token
        const float* Gt = Gp + tid * 26;
        const float inv = rsqrtf(Gt[24] * (1.0f / KDIM) + EPSV);
        const float ap = a_pre[0], aq = a_post[0], ar = a_res[0];
        float* go = gsm[tid];

#pragma unroll
        for (int n = 0; n < 4; ++n) {
            float xpre  = ap * Gt[n] * inv + b_pre[n];
            float xpost = aq * Gt[4 + n] * inv + b_post[n];
            go[n]     = 1.0f / (1.0f + expf(-xpre));
            go[4 + n] = 2.0f / (1.0f + expf(-xpost));
        }
        // Sinkhorn on 4x4 (row-major n*4+m)
        float e[16];
        float mx = -1e30f;
#pragma unroll
        for (int j = 0; j < 16; ++j) {
            float l = ar * Gt[8 + j] * inv + b_res[j];
            e[j] = l;
            mx = fmaxf(mx, l);
        }
#pragma unroll
        for (int j = 0; j < 16; ++j) e[j] = expf(e[j] - mx);
#pragma unroll
        for (int it = 0; it < 5; ++it) {
#pragma unroll
            for (int n = 0; n < 4; ++n) {
                float s = e[n*4] + e[n*4+1] + e[n*4+2] + e[n*4+3] + 1e-6f;
                float rcp = 1.0f / s;
                e[n*4] *= rcp; e[n*4+1] *= rcp; e[n*4+2] *= rcp; e[n*4+3] *= rcp;
            }
#pragma unroll
            for (int m = 0; m < 4; ++m) {
                float s = e[m] + e[4+m] + e[8+m] + e[12+m] + 1e-6f;
                float rcp = 1.0f / s;
                e[m] *= rcp; e[4+m] *= rcp; e[8+m] *= rcp; e[12+m] *= rcp;
            }
        }
#pragma unroll
        for (int j = 0; j < 16; ++j) go[8 + j] = e[j];
    }
    __syncthreads();

    // ===================== Phase 2: combine (warp w -> token w) ==========
    {
        const int tg = tok0 + w;
        float hpre[4], hpost[4], hres[16];
#pragma unroll
        for (int n = 0; n < 4; ++n) { hpre[n] = gsm[w][n]; hpost[n] = gsm[w][4 + n]; }
#pragma unroll
        for (int j = 0; j < 16; ++j) hres[j] = gsm[w][8 + j];

        const float4* op = (const float4*)(outv + (size_t)tg * CDIM);
        float4* xp = (float4*)(xin + (size_t)tg * CDIM);
        float4* up = (float4*)(upd + (size_t)tg * KDIM);
        const float* S = Sf + w * SP;

#pragma unroll
        for (int q = 0; q < 8; ++q) {
            int c4 = lane + 32 * q;
            float4 s0 = *(const float4*)(S +          c4 * 4);
            float4 s1 = *(const float4*)(S + 1024 + c4 * 4);
            float4 s2 = *(const float4*)(S + 2048 + c4 * 4);
            float4 s3 = *(const float4*)(S + 3072 + c4 * 4);
            float4 ov = op[c4];

            float4 x;
            x.x = hpre[0]*s0.x + hpre[1]*s1.x + hpre[2]*s2.x + hpre[3]*s3.x;
            x.y = hpre[0]*s0.y + hpre[1]*s1.y + hpre[2]*s2.y + hpre[3]*s3.y;
            x.z = hpre[0]*s0.z + hpre[1]*s1.z + hpre[2]*s2.z + hpre[3]*s3.z;
            x.w = hpre[0]*s0.w + hpre[1]*s1.w + hpre[2]*s2.w + hpre[3]*s3.w;
            xp[c4] = x;

#pragma unroll
            for (int n = 0; n < 4; ++n) {
                const float h0 = hres[n*4+0], h1 = hres[n*4+1];
                const float h2 = hres[n*4+2], h3 = hres[n*4+3];
                const float hp = hpost[n];
                float4 u;
                u.x = h0*s0.x + h1*s1.x + h2*s2.x + h3*s3.x + hp*ov.x;
                u.y = h0*s0.y + h1*s1.y + h2*s2.y + h3*s3.y + hp*ov.y;
                u.z = h0*s0.z + h1*s1.z + h2*s2.z + h3*s3.z + hp*ov.z;
                u.w = h0*s0.w + h1*s1.w + h2*s2.w + h3*s3.w + hp*ov.w;
                up[n * 256 + c4] = u;
            }
        }
    }
}

// ---------------------------------------------------------------------------
extern "C" void kernel_launch(void* const* d_in, const int* in_sizes, int n_in,
                              void* d_out, int out_size)
{
    const float* stream = (const float*)d_in[0];
    const float* outv   = (const float*)d_in[1];
    const float* w_pre  = (const float*)d_in[2];
    const float* w_post = (const float*)d_in[3];
    const float* w_res  = (const float*)d_in[4];
    const float* b_pre  = (const float*)d_in[5];
    const float* b_post = (const float*)d_in[6];
    const float* b_res  = (const float*)d_in[7];
    const float* a_pre  = (const float*)d_in[8];
    const float* a_post = (const float*)d_in[9];
    const float* a_res  = (const float*)d_in[10];

    float* xin = (float*)d_out;                      // (B,T,C)
    float* upd = xin + (size_t)BT * CDIM;            // (B,T,N,C)

    cudaFuncSetAttribute(fused_mhc, cudaFuncAttributeMaxDynamicSharedMemorySize,
                         SMEM_BYTES);
    fused_mhc<<<BT / TMF, NTF, SMEM_BYTES>>>(stream, outv,
                                             w_pre, w_post, w_res,
                                             b_pre, b_post, b_res,
                                             a_pre, a_post, a_res,
                                             xin, upd);
}

// round 9
// speedup vs baseline: 1.5336x; 1.5336x over previous
#include <cuda_runtime.h>
#include <math.h>

// Problem constants
#define BT     8192      // B*T tokens
#define KDIM   4096      // N*C flattened
#define CDIM   1024      // embed
#define NOUT   24        // 4 pre + 4 post + 16 res
#define EPSV   1e-6f

// K1 tiling
#define TM     32        // tokens per block
#define NT1    256       // threads (8 warps)
#define KC     128       // k-chunk
#define NCH    (KDIM / KC)   // 32 chunks
#define AP     132       // A tile pitch (floats)
#define WPc    132       // W tile pitch (floats)
#define ABUF   (TM * AP)     // 4224 floats
#define WBUF   (NOUT * WPc)  // 3168 floats
#define K1_SMEM ((2 * ABUF + 2 * WBUF) * 4)  // 59136 B

// Gate scratch: per token [0..3]=h_pre, [4..7]=h_post, [8..23]=h_res (n*4+m)
__device__ float g_gates[(size_t)BT * NOUT];

__device__ __forceinline__ void cpa16(unsigned saddr, const void* g) {
    asm volatile("cp.async.cg.shared.global [%0], [%1], 16;"
                 :: "r"(saddr), "l"(g));
}

__device__ __forceinline__ void mma_tf32(float c[4], const unsigned a[4],
                                         const unsigned b[2]) {
    asm volatile(
        "mma.sync.aligned.m16n8k8.row.col.f32.tf32.tf32.f32 "
        "{%0,%1,%2,%3}, {%4,%5,%6,%7}, {%8,%9}, {%0,%1,%2,%3};"
        : "+f"(c[0]), "+f"(c[1]), "+f"(c[2]), "+f"(c[3])
        : "r"(a[0]), "r"(a[1]), "r"(a[2]), "r"(a[3]), "r"(b[0]), "r"(b[1]));
}

// ---------------------------------------------------------------------------
// K1: gate GEMM (tf32 mma, raw fp32 operands = tf32 truncation) with
// cp.async double-buffered staging. k split across 8 warps (warp w: cols
// 16w..16w+15 of each 128-chunk). Sumsq from A-fragments. Fused gate math.
// ---------------------------------------------------------------------------
__global__ void __launch_bounds__(NT1, 2)
k1_gates(const float* __restrict__ stream,
         const float* __restrict__ w_pre,
         const float* __restrict__ w_post,
         const float* __restrict__ w_res,
         const float* __restrict__ b_pre,
         const float* __restrict__ b_post,
         const float* __restrict__ b_res,
         const float* __restrict__ a_pre,
         const float* __restrict__ a_post,
         const float* __restrict__ a_res)
{
    extern __shared__ float sm[];
    const unsigned sbase = (unsigned)__cvta_generic_to_shared(sm);

    const int tid  = threadIdx.x;
    const int lane = tid & 31;
    const int w    = tid >> 5;          // warp id = k-slice owner
    const int gid  = lane >> 2;         // mma group id (0..7)
    const int tig  = lane & 3;          // thread-in-group (0..3)
    const int tok0 = blockIdx.x * TM;

    // Precomputed staging indices (row/col constant across chunks)
    const int sArow = tid >> 5;         // stream rows tid>>5 + 8i? no: f=tid+256i
    (void)sArow;

    // stage chunk ch into buffer buf (cp.async only, no commit)
    auto stage = [&](int ch, int buf) {
        // stream: 32 x 128 = 1024 float4, 4 per thread
#pragma unroll
        for (int i = 0; i < 4; ++i) {
            int f   = tid + NT1 * i;    // 0..1023
            int row = f >> 5;           // 0..31
            int c4  = f & 31;
            unsigned dst = sbase + (buf * ABUF + row * AP + c4 * 4) * 4;
            cpa16(dst, stream + (size_t)(tok0 + row) * KDIM + ch * KC + c4 * 4);
        }
        // weights: 24 x 128 = 768 float4, 3 per thread
#pragma unroll
        for (int j = 0; j < 3; ++j) {
            int f   = tid + NT1 * j;    // 0..767
            int row = f >> 5;           // 0..23
            int c4  = f & 31;
            const float* src = (row < 4)  ? (w_pre  + (size_t)row * KDIM)
                             : (row < 8)  ? (w_post + (size_t)(row - 4) * KDIM)
                                          : (w_res  + (size_t)(row - 8) * KDIM);
            unsigned dst = sbase + (2 * ABUF + buf * WBUF + row * WPc + c4 * 4) * 4;
            cpa16(dst, src + ch * KC + c4 * 4);
        }
    };

    float c[2][3][4];
#pragma unroll
    for (int mt = 0; mt < 2; ++mt)
#pragma unroll
        for (int nt = 0; nt < 3; ++nt)
#pragma unroll
            for (int q = 0; q < 4; ++q) c[mt][nt][q] = 0.f;
    float ss[4] = {0.f, 0.f, 0.f, 0.f};   // rows gid, gid+8, gid+16, gid+24

    // prologue: chunk 0 -> buf 0
    stage(0, 0);
    asm volatile("cp.async.commit_group;");

    for (int ch = 0; ch < NCH; ++ch) {
        asm volatile("cp.async.wait_group 0;");
        __syncthreads();
        if (ch + 1 < NCH) {
            stage(ch + 1, (ch + 1) & 1);
            asm volatile("cp.async.commit_group;");
        }
        const unsigned* As = (const unsigned*)(sm + (ch & 1) * ABUF);
        const unsigned* Ws = (const unsigned*)(sm + 2 * ABUF + (ch & 1) * WBUF);

#pragma unroll
        for (int s = 0; s < 2; ++s) {
            const int kk = w * 16 + 8 * s;
            unsigned a[2][4], b[3][2];
#pragma unroll
            for (int mt = 0; mt < 2; ++mt) {
                const unsigned* A0 = As + (mt * 16 + gid) * AP + kk + tig;
                a[mt][0] = A0[0];
                a[mt][2] = A0[4];
                a[mt][1] = A0[8 * AP];
                a[mt][3] = A0[8 * AP + 4];
            }
#pragma unroll
            for (int nt = 0; nt < 3; ++nt) {
                const unsigned* B0 = Ws + (nt * 8 + gid) * WPc + kk + tig;
                b[nt][0] = B0[0];
                b[nt][1] = B0[4];
            }
            // sumsq from exact fp32 fragment values
            {
                float f00 = __uint_as_float(a[0][0]), f02 = __uint_as_float(a[0][2]);
                float f01 = __uint_as_float(a[0][1]), f03 = __uint_as_float(a[0][3]);
                float f10 = __uint_as_float(a[1][0]), f12 = __uint_as_float(a[1][2]);
                float f11 = __uint_as_float(a[1][1]), f13 = __uint_as_float(a[1][3]);
                ss[0] += f00 * f00 + f02 * f02;
                ss[1] += f01 * f01 + f03 * f03;
                ss[2] += f10 * f10 + f12 * f12;
                ss[3] += f11 * f11 + f13 * f13;
            }
#pragma unroll
            for (int mt = 0; mt < 2; ++mt)
#pragma unroll
                for (int nt = 0; nt < 3; ++nt)
                    mma_tf32(c[mt][nt], a[mt], b[nt]);
        }
    }

    // reduce sumsq over tig lanes (bits 0,1 of lane)
#pragma unroll
    for (int i = 0; i < 4; ++i) {
        ss[i] += __shfl_xor_sync(0xffffffffu, ss[i], 1);
        ss[i] += __shfl_xor_sync(0xffffffffu, ss[i], 2);
    }

    __syncthreads();   // staging buffers dead; alias epilogue buffers
    float* red = sm;                    // [8 warps][32 tok][26] = 6656
    float* ssb = sm + 6656;             // [8 warps][32 tok]     = 256
    float* G   = sm + 6912;             // [32 tok][26]          = 832

#pragma unroll
    for (int mt = 0; mt < 2; ++mt)
#pragma unroll
        for (int nt = 0; nt < 3; ++nt) {
            int t0 = mt * 16 + gid, o0 = nt * 8 + 2 * tig;
            red[(w * TM + t0)     * 26 + o0]     = c[mt][nt][0];
            red[(w * TM + t0)     * 26 + o0 + 1] = c[mt][nt][1];
            red[(w * TM + t0 + 8) * 26 + o0]     = c[mt][nt][2];
            red[(w * TM + t0 + 8) * 26 + o0 + 1] = c[mt][nt][3];
        }
    if (tig == 0) {
#pragma unroll
        for (int i = 0; i < 4; ++i)
            ssb[w * TM + gid + 8 * i] = ss[i];
    }
    __syncthreads();

    for (int idx = tid; idx < TM * NOUT; idx += NT1) {
        int t = idx / NOUT, o = idx - t * NOUT;
        float s = 0.f;
#pragma unroll
        for (int ww = 0; ww < 8; ++ww)
            s += red[(ww * TM + t) * 26 + o];
        G[t * 26 + o] = s;
    }
    if (tid < TM) {
        float s = 0.f;
#pragma unroll
        for (int ww = 0; ww < 8; ++ww) s += ssb[ww * TM + tid];
        G[tid * 26 + 24] = s;
    }
    __syncthreads();

    // ---- gate math: one thread per token ----
    if (tid < TM) {
        const float* Gt = G + tid * 26;
        const float inv = rsqrtf(Gt[24] * (1.0f / KDIM) + EPSV);
        const float ap = a_pre[0], aq = a_post[0], ar = a_res[0];
        const int t = tok0 + tid;
        float* gout = g_gates + (size_t)t * NOUT;

#pragma unroll
        for (int n = 0; n < 4; ++n) {
            float xpre  = ap * Gt[n] * inv + b_pre[n];
            float xpost = aq * Gt[4 + n] * inv + b_post[n];
            gout[n]     = 1.0f / (1.0f + expf(-xpre));
            gout[4 + n] = 2.0f / (1.0f + expf(-xpost));
        }
        float e[16];
        float mx = -1e30f;
#pragma unroll
        for (int j = 0; j < 16; ++j) {
            float l = ar * Gt[8 + j] * inv + b_res[j];
            e[j] = l;
            mx = fmaxf(mx, l);
        }
#pragma unroll
        for (int j = 0; j < 16; ++j) e[j] = expf(e[j] - mx);
#pragma unroll
        for (int it = 0; it < 5; ++it) {
#pragma unroll
            for (int n = 0; n < 4; ++n) {
                float s = e[n*4] + e[n*4+1] + e[n*4+2] + e[n*4+3] + 1e-6f;
                float rcp = 1.0f / s;
                e[n*4] *= rcp; e[n*4+1] *= rcp; e[n*4+2] *= rcp; e[n*4+3] *= rcp;
            }
#pragma unroll
            for (int m = 0; m < 4; ++m) {
                float s = e[m] + e[4+m] + e[8+m] + e[12+m] + 1e-6f;
                float rcp = 1.0f / s;
                e[m] *= rcp; e[4+m] *= rcp; e[8+m] *= rcp; e[12+m] *= rcp;
            }
        }
#pragma unroll
        for (int j = 0; j < 16; ++j) gout[8 + j] = e[j];
    }
}

// ---------------------------------------------------------------------------
// K2: streaming combine (measured at DRAM roofline — unchanged).
// ---------------------------------------------------------------------------
__global__ void __launch_bounds__(256)
k2_combine(const float* __restrict__ stream,
           const float* __restrict__ outv,
           float* __restrict__ xin,
           float* __restrict__ upd)
{
    __shared__ float g[NOUT];
    const int t = blockIdx.x;
    const int tid = threadIdx.x;
    if (tid < NOUT) g[tid] = g_gates[(size_t)t * NOUT + tid];
    __syncthreads();

    const float4* sp = (const float4*)(stream + (size_t)t * KDIM);
    float4 s0 = sp[tid];
    float4 s1 = sp[256 + tid];
    float4 s2 = sp[512 + tid];
    float4 s3 = sp[768 + tid];
    float4 ov = ((const float4*)(outv + (size_t)t * CDIM))[tid];

    float4 x;
    x.x = g[0]*s0.x + g[1]*s1.x + g[2]*s2.x + g[3]*s3.x;
    x.y = g[0]*s0.y + g[1]*s1.y + g[2]*s2.y + g[3]*s3.y;
    x.z = g[0]*s0.z + g[1]*s1.z + g[2]*s2.z + g[3]*s3.z;
    x.w = g[0]*s0.w + g[1]*s1.w + g[2]*s2.w + g[3]*s3.w;
    ((float4*)(xin + (size_t)t * CDIM))[tid] = x;

    float4* up = (float4*)(upd + (size_t)t * KDIM);
#pragma unroll
    for (int n = 0; n < 4; ++n) {
        const float h0 = g[8 + n*4 + 0];
        const float h1 = g[8 + n*4 + 1];
        const float h2 = g[8 + n*4 + 2];
        const float h3 = g[8 + n*4 + 3];
        const float hp = g[4 + n];
        float4 u;
        u.x = h0*s0.x + h1*s1.x + h2*s2.x + h3*s3.x + hp*ov.x;
        u.y = h0*s0.y + h1*s1.y + h2*s2.y + h3*s3.y + hp*ov.y;
        u.z = h0*s0.z + h1*s1.z + h2*s2.z + h3*s3.z + hp*ov.z;
        u.w = h0*s0.w + h1*s1.w + h2*s2.w + h3*s3.w + hp*ov.w;
        up[n * 256 + tid] = u;
    }
}

// ---------------------------------------------------------------------------
extern "C" void kernel_launch(void* const* d_in, const int* in_sizes, int n_in,
                              void* d_out, int out_size)
{
    const float* stream = (const float*)d_in[0];
    const float* outv   = (const float*)d_in[1];
    const float* w_pre  = (const float*)d_in[2];
    const float* w_post = (const float*)d_in[3];
    const float* w_res  = (const float*)d_in[4];
    const float* b_pre  = (const float*)d_in[5];
    const float* b_post = (const float*)d_in[6];
    const float* b_res  = (const float*)d_in[7];
    const float* a_pre  = (const float*)d_in[8];
    const float* a_post = (const float*)d_in[9];
    const float* a_res  = (const float*)d_in[10];

    float* xin = (float*)d_out;                      // (B,T,C)
    float* upd = xin + (size_t)BT * CDIM;            // (B,T,N,C)

    cudaFuncSetAttribute(k1_gates, cudaFuncAttributeMaxDynamicSharedMemorySize,
                         K1_SMEM);
    k1_gates<<<BT / TM, NT1, K1_SMEM>>>(stream, w_pre, w_post, w_res,
                                        b_pre, b_post, b_res,
                                        a_pre, a_post, a_res);
    k2_combine<<<BT, 256>>>(stream, outv, xin, upd);
}